// round 3
// baseline (speedup 1.0000x reference)
#include <cuda_runtime.h>

// CombPool2d: out = (w_avg^2)*avg_pool2x2(x) + (w_max^2)*max_pool2x2(x)
// x: (16,192,224,224) f32, w_avg/w_max: (1,192,1,1), out: (16,192,112,112)
//
// Streaming kernel, ~771 MB total traffic -> HBM roofline ~100-120 us.
// Each thread: 4 output pixels (1 float4 store), 4x LDG.128 (64B) input.

#define IH 224
#define IW 224
#define OH 112
#define OW 112
#define C_CH 192
#define QW (OW / 4)          // 28 float4-quads per output row

__global__ void __launch_bounds__(256)
combpool2d_kernel(const float* __restrict__ x,
                  const float* __restrict__ w_avg,
                  const float* __restrict__ w_max,
                  float* __restrict__ out,
                  int total_quads)
{
    int i = blockIdx.x * blockDim.x + threadIdx.x;
    if (i >= total_quads) return;

    // i -> (bc, oh, qw) with compile-time-constant divisors
    int qw = i % QW;
    int t  = i / QW;
    int oh = t % OH;
    int bc = t / OH;           // fused batch*channel, 0..3071
    int c  = bc % C_CH;

    float wa = __ldg(w_avg + c);
    float wm = __ldg(w_max + c);
    wa = wa * wa * 0.25f;      // fold 1/(K*K) into the avg coefficient
    wm = wm * wm;

    const float* row0 = x + (size_t)bc * (IH * IW) + (size_t)(2 * oh) * IW + qw * 8;
    const float* row1 = row0 + IW;

    // 4 front-batched 128-bit loads (MLP=4)
    float4 a0 = *reinterpret_cast<const float4*>(row0);
    float4 a1 = *reinterpret_cast<const float4*>(row0 + 4);
    float4 b0 = *reinterpret_cast<const float4*>(row1);
    float4 b1 = *reinterpret_cast<const float4*>(row1 + 4);

    float4 o;
    o.x = wa * (a0.x + a0.y + b0.x + b0.y)
        + wm * fmaxf(fmaxf(a0.x, a0.y), fmaxf(b0.x, b0.y));
    o.y = wa * (a0.z + a0.w + b0.z + b0.w)
        + wm * fmaxf(fmaxf(a0.z, a0.w), fmaxf(b0.z, b0.w));
    o.z = wa * (a1.x + a1.y + b1.x + b1.y)
        + wm * fmaxf(fmaxf(a1.x, a1.y), fmaxf(b1.x, b1.y));
    o.w = wa * (a1.z + a1.w + b1.z + b1.w)
        + wm * fmaxf(fmaxf(a1.z, a1.w), fmaxf(b1.z, b1.w));

    *reinterpret_cast<float4*>(out + (size_t)bc * (OH * OW) + (size_t)oh * OW + qw * 4) = o;
}

extern "C" void kernel_launch(void* const* d_in, const int* in_sizes, int n_in,
                              void* d_out, int out_size)
{
    const float* x     = (const float*)d_in[0];
    const float* w_avg = (const float*)d_in[1];
    const float* w_max = (const float*)d_in[2];
    float* out = (float*)d_out;

    int total_quads = out_size / 4;               // 9,633,792
    int threads = 256;
    int blocks = (total_quads + threads - 1) / threads;
    combpool2d_kernel<<<blocks, threads>>>(x, w_avg, w_max, out, total_quads);
}